// round 16
// baseline (speedup 1.0000x reference)
#include <cuda_runtime.h>
#include <cstdint>

#define SEQ    2048
#define BATCH  2
#define DM     1024
#define NH     16
#define DH     64
#define MROWS  (SEQ * BATCH)      // 4096
#define QKV_N  (3 * DM)           // 3072

// Scratch (allocation-free rule: __device__ globals)
__device__ float g_qkv[(size_t)MROWS * QKV_N];   // (t*B+b, 3072)  q|k|v
__device__ float g_av [(size_t)MROWS * DM];      // (t*B+b, 1024)

// ---------------------------------------------------------------------------
// bf16x2 helpers
// ---------------------------------------------------------------------------
__device__ __forceinline__ void split2bf(float x, float y, uint32_t& h, uint32_t& l) {
    asm("cvt.rn.bf16x2.f32 %0, %1, %2;" : "=r"(h) : "f"(y), "f"(x));
    const float hx = __uint_as_float(h << 16);
    const float hy = __uint_as_float(h & 0xFFFF0000u);
    asm("cvt.rn.bf16x2.f32 %0, %1, %2;" : "=r"(l) : "f"(y - hy), "f"(x - hx));
}
__device__ __forceinline__ void mma_bf16(float* c, const uint32_t* a, const uint32_t* b) {
    asm volatile(
        "mma.sync.aligned.m16n8k16.row.col.f32.bf16.bf16.f32 "
        "{%0,%1,%2,%3}, {%4,%5,%6,%7}, {%8,%9}, {%0,%1,%2,%3};"
        : "+f"(c[0]), "+f"(c[1]), "+f"(c[2]), "+f"(c[3])
        : "r"(a[0]), "r"(a[1]), "r"(a[2]), "r"(a[3]), "r"(b[0]), "r"(b[1]));
}
__device__ __forceinline__ void ldsm4(uint32_t* r, uint32_t saddr) {
    asm volatile("ldmatrix.sync.aligned.m8n8.x4.shared.b16 {%0,%1,%2,%3}, [%4];"
                 : "=r"(r[0]), "=r"(r[1]), "=r"(r[2]), "=r"(r[3]) : "r"(saddr));
}

// ===========================================================================
// bf16x2 (3-product) warp-MMA GEMM, ldmatrix fragments, ks ping-pong.
// CTA 128x128, 8 warps (64x32 each), K-chunks of 32 (= 2 x k16 MMA steps).
// ===========================================================================
#define PS 20
#define PTILE (128 * PS)
#define PSTAGE (4 * PTILE)                    // A0,A1,B0,B1
#define GEMM_SMEM (2 * PSTAGE * 4)            // 81920 B (double buffered)

__global__ __launch_bounds__(256, 1) void gemm_bf16x2(
    const float* __restrict__ A, const float* __restrict__ Bw,
    const float* __restrict__ bias, float* __restrict__ C,
    int M, int N, int K)
{
    extern __shared__ uint32_t smu[];
    const uint32_t smem_base = (uint32_t)__cvta_generic_to_shared(smu);

    const int tid  = threadIdx.x;
    const int wid  = tid >> 5;
    const int lane = tid & 31;
    const int gid  = lane >> 2;
    const int tig  = lane & 3;
    const int mw   = (wid & 1) * 64;
    const int nw   = (wid >> 1) * 32;
    const int row0 = blockIdx.y * 128;
    const int col0 = blockIdx.x * 128;

    float acc[4][4][4];
#pragma unroll
    for (int i = 0; i < 4; i++)
#pragma unroll
        for (int j = 0; j < 4; j++)
#pragma unroll
            for (int e = 0; e < 4; e++) acc[i][j][e] = 0.f;

    const int ldr = tid >> 3;           // 0..31 row slice
    const int ldc = (tid & 7) << 2;     // float col 0..28
    const int lcp = (tid & 7) << 1;     // packed col 0..14

    // ldmatrix per-lane address components
    const int a_row = ((lane >> 3) & 1) * 8 + (lane & 7);  // + mw + i*16
    const int a_col = (lane >> 4) * 4;                     // + ks*8
    const int b_row = (lane >> 4) * 8 + (lane & 7);        // + nw + jp*16
    const int b_col = ((lane >> 3) & 1) * 4;               // + ks*8

    float4 pa[4], pb[4];
#pragma unroll
    for (int it = 0; it < 4; it++) {
        const int r = ldr + it * 32;
        pa[it] = *(const float4*)(A  + (size_t)(row0 + r) * K + ldc);
        pb[it] = *(const float4*)(Bw + (size_t)(col0 + r) * K + ldc);
    }
    {
        uint32_t* A0 = smu;            uint32_t* A1 = A0 + PTILE;
        uint32_t* B0 = A1 + PTILE;     uint32_t* B1 = B0 + PTILE;
#pragma unroll
        for (int it = 0; it < 4; it++) {
            const int r = ldr + it * 32;
            uint32_t h0, l0, h1, l1;
            split2bf(pa[it].x, pa[it].y, h0, l0);
            split2bf(pa[it].z, pa[it].w, h1, l1);
            *(uint2*)(A0 + r * PS + lcp) = make_uint2(h0, h1);
            *(uint2*)(A1 + r * PS + lcp) = make_uint2(l0, l1);
            split2bf(pb[it].x, pb[it].y, h0, l0);
            split2bf(pb[it].z, pb[it].w, h1, l1);
            *(uint2*)(B0 + r * PS + lcp) = make_uint2(h0, h1);
            *(uint2*)(B1 + r * PS + lcp) = make_uint2(l0, l1);
        }
    }
    const int KCH = K >> 5;
    if (KCH > 1) {
#pragma unroll
        for (int it = 0; it < 4; it++) {
            const int r = ldr + it * 32;
            pa[it] = *(const float4*)(A  + (size_t)(row0 + r) * K + 32 + ldc);
            pb[it] = *(const float4*)(Bw + (size_t)(col0 + r) * K + 32 + ldc);
        }
    }
    __syncthreads();

    // Fragment ping-pong sets: f0 = ks0, f1 = ks1 of the current buffer.
    uint32_t afh0[4][4], afl0[4][4], bfh0[2][4], bfl0[2][4];
    uint32_t afh1[4][4], afl1[4][4], bfh1[2][4], bfl1[2][4];

    // Prologue: load f0 from buffer 0.
    {
        const uint32_t A0a = smem_base;
        const uint32_t A1a = smem_base + PTILE * 4;
        const uint32_t B0a = smem_base + 2 * PTILE * 4;
        const uint32_t B1a = smem_base + 3 * PTILE * 4;
#pragma unroll
        for (int i = 0; i < 4; i++) {
            const uint32_t off = (uint32_t)(((mw + i * 16 + a_row) * PS) + a_col) * 4;
            ldsm4(afh0[i], A0a + off);
            ldsm4(afl0[i], A1a + off);
        }
#pragma unroll
        for (int jp = 0; jp < 2; jp++) {
            const uint32_t off = (uint32_t)(((nw + jp * 16 + b_row) * PS) + b_col) * 4;
            ldsm4(bfh0[jp], B0a + off);
            ldsm4(bfl0[jp], B1a + off);
        }
    }

    for (int kt = 0; kt < KCH; kt++) {
        const uint32_t cur  = smem_base + (uint32_t)((kt & 1) * PSTAGE) * 4;
        const uint32_t nxtb = smem_base + (uint32_t)(((kt + 1) & 1) * PSTAGE) * 4;
        uint32_t* nxt = smu + ((kt + 1) & 1) * PSTAGE;

        // 1. Load f1 (ks=1) fragments from the current buffer.
        {
            const uint32_t A0a = cur;
            const uint32_t A1a = cur + PTILE * 4;
            const uint32_t B0a = cur + 2 * PTILE * 4;
            const uint32_t B1a = cur + 3 * PTILE * 4;
#pragma unroll
            for (int i = 0; i < 4; i++) {
                const uint32_t off =
                    (uint32_t)(((mw + i * 16 + a_row) * PS) + 8 + a_col) * 4;
                ldsm4(afh1[i], A0a + off);
                ldsm4(afl1[i], A1a + off);
            }
#pragma unroll
            for (int jp = 0; jp < 2; jp++) {
                const uint32_t off =
                    (uint32_t)(((nw + jp * 16 + b_row) * PS) + 8 + b_col) * 4;
                ldsm4(bfh1[jp], B0a + off);
                ldsm4(bfl1[jp], B1a + off);
            }
        }

        // 2. Convert + store next chunk into the other buffer.
        if (kt + 1 < KCH) {
            uint32_t* A0 = nxt;        uint32_t* A1 = A0 + PTILE;
            uint32_t* B0 = A1 + PTILE; uint32_t* B1 = B0 + PTILE;
#pragma unroll
            for (int it = 0; it < 4; it++) {
                const int r = ldr + it * 32;
                uint32_t h0, l0, h1, l1;
                split2bf(pa[it].x, pa[it].y, h0, l0);
                split2bf(pa[it].z, pa[it].w, h1, l1);
                *(uint2*)(A0 + r * PS + lcp) = make_uint2(h0, h1);
                *(uint2*)(A1 + r * PS + lcp) = make_uint2(l0, l1);
                split2bf(pb[it].x, pb[it].y, h0, l0);
                split2bf(pb[it].z, pb[it].w, h1, l1);
                *(uint2*)(B0 + r * PS + lcp) = make_uint2(h0, h1);
                *(uint2*)(B1 + r * PS + lcp) = make_uint2(l0, l1);
            }
        }
        // 3. Global prefetch for chunk kt+2.
        if (kt + 2 < KCH) {
            const int k0n = (kt + 2) << 5;
#pragma unroll
            for (int it = 0; it < 4; it++) {
                const int r = ldr + it * 32;
                pa[it] = *(const float4*)(A  + (size_t)(row0 + r) * K + k0n + ldc);
                pb[it] = *(const float4*)(Bw + (size_t)(col0 + r) * K + k0n + ldc);
            }
        }

        // 4. MMA on f0 (loaded last iteration / prologue).
#pragma unroll
        for (int i = 0; i < 4; i++)
#pragma unroll
            for (int j = 0; j < 4; j++) {
                const uint32_t* bh = &bfh0[j >> 1][(j & 1) * 2];
                const uint32_t* bl = &bfl0[j >> 1][(j & 1) * 2];
                mma_bf16(acc[i][j], afh0[i], bh);
                mma_bf16(acc[i][j], afh0[i], bl);
                mma_bf16(acc[i][j], afl0[i], bh);
            }
        // 5. MMA on f1 (loaded at step 1).
#pragma unroll
        for (int i = 0; i < 4; i++)
#pragma unroll
            for (int j = 0; j < 4; j++) {
                const uint32_t* bh = &bfh1[j >> 1][(j & 1) * 2];
                const uint32_t* bl = &bfl1[j >> 1][(j & 1) * 2];
                mma_bf16(acc[i][j], afh1[i], bh);
                mma_bf16(acc[i][j], afh1[i], bl);
                mma_bf16(acc[i][j], afl1[i], bh);
            }
        __syncthreads();

        // 6. Load f0 (ks=0) fragments from the next buffer.
        if (kt + 1 < KCH) {
            const uint32_t A0a = nxtb;
            const uint32_t A1a = nxtb + PTILE * 4;
            const uint32_t B0a = nxtb + 2 * PTILE * 4;
            const uint32_t B1a = nxtb + 3 * PTILE * 4;
#pragma unroll
            for (int i = 0; i < 4; i++) {
                const uint32_t off =
                    (uint32_t)(((mw + i * 16 + a_row) * PS) + a_col) * 4;
                ldsm4(afh0[i], A0a + off);
                ldsm4(afl0[i], A1a + off);
            }
#pragma unroll
            for (int jp = 0; jp < 2; jp++) {
                const uint32_t off =
                    (uint32_t)(((nw + jp * 16 + b_row) * PS) + b_col) * 4;
                ldsm4(bfh0[jp], B0a + off);
                ldsm4(bfl0[jp], B1a + off);
            }
        }
    }

#pragma unroll
    for (int i = 0; i < 4; i++) {
        const int r = row0 + mw + i * 16 + gid;
#pragma unroll
        for (int j = 0; j < 4; j++) {
            const int ccol = col0 + nw + j * 8 + tig * 2;
            float2 v0, v1;
            v0.x = acc[i][j][0] + bias[ccol];
            v0.y = acc[i][j][1] + bias[ccol + 1];
            v1.x = acc[i][j][2] + bias[ccol];
            v1.y = acc[i][j][3] + bias[ccol + 1];
            *(float2*)(C + (size_t)r * N + ccol)       = v0;
            *(float2*)(C + (size_t)(r + 8) * N + ccol) = v1;
        }
    }
}

// ===========================================================================
// bf16x2 tensor-core flash attention (exact R11 version).
// ===========================================================================
#define KS_ 36
#define VS_ 72
#define K_TILE (64 * KS_)     // 2304 u32
#define V_TILE (32 * VS_)     // 2304 u32
#define ATT_SMEM_BYTES ((4 * K_TILE + 2 * V_TILE) * 4)   // 55296 B

__global__ __launch_bounds__(128, 2) void flash_attn_tc(
    const float* __restrict__ qkv, const int* __restrict__ causal_flag,
    float* __restrict__ av)
{
    extern __shared__ uint32_t smu[];
    uint32_t* K0 = smu;
    uint32_t* K1 = K0 + K_TILE;
    uint32_t* P0 = K1 + K_TILE;
    uint32_t* P1 = P0 + K_TILE;
    uint32_t* V0 = P1 + K_TILE;
    uint32_t* V1 = V0 + V_TILE;
    const uint32_t smem_base = (uint32_t)__cvta_generic_to_shared(smu);
    const uint32_t K0a = smem_base;
    const uint32_t K1a = smem_base + (uint32_t)K_TILE * 4;
    const uint32_t P0a = smem_base + (uint32_t)(2 * K_TILE) * 4;
    const uint32_t P1a = smem_base + (uint32_t)(3 * K_TILE) * 4;

    const int tid  = threadIdx.x;
    const int wid  = tid >> 5;
    const int lane = tid & 31;
    const int gid  = lane >> 2;
    const int tig  = lane & 3;
    const int qt   = blockIdx.x;
    const int b    = blockIdx.y >> 4;
    const int h    = blockIdx.y & 15;
    const int is_causal = *causal_flag;

    const int klr = tid >> 4;            // base row 0..7
    const int kd4 = (tid & 15) << 2;     // float col
    const int kcp = (tid & 15) << 1;     // packed col
    const int vsp = tid >> 5;            // base packed row 0..3
    const int vd2 = (lane) << 1;         // uint32 col 0..62

    const int kb_row = (lane >> 4) * 8 + (lane & 7);       // + jp*16
    const int kb_col = ((lane >> 3) & 1) * 4;              // + ks*8
    const int pa_row = wid * 16 + ((lane >> 3) & 1) * 8 + (lane & 7);
    const int pa_col = (lane >> 4) * 4;                    // + ks*8

    uint32_t qp0[4][4], qp1[4][4];
    {
        const int r0 = qt * 64 + wid * 16 + gid;
        const float* q0 = qkv + ((size_t)(r0 * BATCH + b)) * QKV_N + h * DH;
        const float* q8 = q0 + (size_t)8 * BATCH * QKV_N;
#pragma unroll
        for (int ks = 0; ks < 4; ks++) {
            const float2 qa = *(const float2*)(q0 + ks * 16 + tig * 2);
            const float2 qb = *(const float2*)(q8 + ks * 16 + tig * 2);
            const float2 qc = *(const float2*)(q0 + ks * 16 + tig * 2 + 8);
            const float2 qd = *(const float2*)(q8 + ks * 16 + tig * 2 + 8);
            split2bf(qa.x, qa.y, qp0[ks][0], qp1[ks][0]);
            split2bf(qb.x, qb.y, qp0[ks][1], qp1[ks][1]);
            split2bf(qc.x, qc.y, qp0[ks][2], qp1[ks][2]);
            split2bf(qd.x, qd.y, qp0[ks][3], qp1[ks][3]);
        }
    }

    float4 kreg[8];
    float2 vra[8], vrb[8];
#pragma unroll
    for (int it = 0; it < 8; it++) {
        const int kr = klr + it * 8;
        kreg[it] = *(const float4*)(
            qkv + ((size_t)(kr * BATCH + b)) * QKV_N + h * DH + kd4 + DM);
        const int sp = vsp + it * 4;
        const float* vb0 =
            qkv + ((size_t)((2 * sp) * BATCH + b)) * QKV_N + h * DH + vd2 + 2 * DM;
        vra[it] = *(const float2*)(vb0);
        vrb[it] = *(const float2*)(vb0 + (size_t)BATCH * QKV_N);
    }

    float o[8][4];
#pragma unroll
    for (int j = 0; j < 8; j++)
#pragma unroll
        for (int e = 0; e < 4; e++) o[j][e] = 0.f;
    float m0 = -1e30f, m1 = -1e30f, l0 = 0.f, l1 = 0.f;

    const int kt_end = is_causal ? qt : (SEQ / 64 - 1);

    for (int kt = 0; kt <= kt_end; kt++) {
        __syncthreads();
#pragma unroll
        for (int it = 0; it < 8; it++) {
            const int kr = klr + it * 8;
            uint32_t h0, l0_, h1, l1_;
            split2bf(kreg[it].x, kreg[it].y, h0, l0_);
            split2bf(kreg[it].z, kreg[it].w, h1, l1_);
            *(uint2*)(K0 + kr * KS_ + kcp) = make_uint2(h0, h1);
            *(uint2*)(K1 + kr * KS_ + kcp) = make_uint2(l0_, l1_);
            const int sp = vsp + it * 4;
            split2bf(vra[it].x, vrb[it].x, h0, l0_);
            split2bf(vra[it].y, vrb[it].y, h1, l1_);
            *(uint2*)(V0 + sp * VS_ + vd2) = make_uint2(h0, h1);
            *(uint2*)(V1 + sp * VS_ + vd2) = make_uint2(l0_, l1_);
        }
        __syncthreads();

        if (kt < kt_end) {
#pragma unroll
            for (int it = 0; it < 8; it++) {
                const int kr = (kt + 1) * 64 + klr + it * 8;
                kreg[it] = *(const float4*)(
                    qkv + ((size_t)(kr * BATCH + b)) * QKV_N + h * DH + kd4 + DM);
            }
        }

        float s[8][4];
#pragma unroll
        for (int j = 0; j < 8; j++)
#pragma unroll
            for (int e = 0; e < 4; e++) s[j][e] = 0.f;

#pragma unroll
        for (int ks = 0; ks < 4; ks++) {
            uint32_t kf[4][4], kl[4][4];
#pragma unroll
            for (int jp = 0; jp < 4; jp++) {
                const uint32_t off =
                    (uint32_t)(((jp * 16 + kb_row) * KS_) + ks * 8 + kb_col) * 4;
                ldsm4(kf[jp], K0a + off);
                ldsm4(kl[jp], K1a + off);
            }
#pragma unroll
            for (int j = 0; j < 8; j++) {
                const uint32_t* bh = &kf[j >> 1][(j & 1) * 2];
                const uint32_t* bl = &kl[j >> 1][(j & 1) * 2];
                mma_bf16(s[j], qp0[ks], bh);
                mma_bf16(s[j], qp0[ks], bl);
                mma_bf16(s[j], qp1[ks], bh);
            }
        }

#pragma unroll
        for (int j = 0; j < 8; j++)
#pragma unroll
            for (int e = 0; e < 4; e++) s[j][e] *= 8.0f;

        if (is_causal && kt == qt) {
            const int r0 = wid * 16 + gid;
#pragma unroll
            for (int j = 0; j < 8; j++) {
                const int c = j * 8 + tig * 2;
                if (c     > r0)     s[j][0] = -1e30f;
                if (c + 1 > r0)     s[j][1] = -1e30f;
                if (c     > r0 + 8) s[j][2] = -1e30f;
                if (c + 1 > r0 + 8) s[j][3] = -1e30f;
            }
        }

        float rm0 = -1e30f, rm1 = -1e30f;
#pragma unroll
        for (int j = 0; j < 8; j++) {
            rm0 = fmaxf(rm0, fmaxf(s[j][0], s[j][1]));
            rm1 = fmaxf(rm1, fmaxf(s[j][2], s[j][3]));
        }
        rm0 = fmaxf(rm0, __shfl_xor_sync(0xffffffffu, rm0, 1));
        rm0 = fmaxf(rm0, __shfl_xor_sync(0xffffffffu, rm0, 2));
        rm1 = fmaxf(rm1, __shfl_xor_sync(0xffffffffu, rm1, 1));
        rm1 = fmaxf(rm1, __shfl_xor_sync(0xffffffffu, rm1, 2));

        const float mn0 = fmaxf(m0, rm0);
        const float mn1 = fmaxf(m1, rm1);
        const float corr0 = __expf(m0 - mn0);
        const float corr1 = __expf(m1 - mn1);

        float rs0 = 0.f, rs1 = 0.f;
        const int prow = wid * 16 + gid;
#pragma unroll
        for (int j = 0; j < 8; j++) {
            const float p00 = __expf(s[j][0] - mn0);
            const float p01 = __expf(s[j][1] - mn0);
            const float p10 = __expf(s[j][2] - mn1);
            const float p11 = __expf(s[j][3] - mn1);
            rs0 += p00 + p01;
            rs1 += p10 + p11;
            uint32_t hh, ll;
            split2bf(p00, p01, hh, ll);
            P0[prow * KS_ + j * 4 + tig] = hh;
            P1[prow * KS_ + j * 4 + tig] = ll;
            split2bf(p10, p11, hh, ll);
            P0[(prow + 8) * KS_ + j * 4 + tig] = hh;
            P1[(prow + 8) * KS_ + j * 4 + tig] = ll;
        }
        rs0 += __shfl_xor_sync(0xffffffffu, rs0, 1);
        rs0 += __shfl_xor_sync(0xffffffffu, rs0, 2);
        rs1 += __shfl_xor_sync(0xffffffffu, rs1, 1);
        rs1 += __shfl_xor_sync(0xffffffffu, rs1, 2);

        l0 = l0 * corr0 + rs0;
        l1 = l1 * corr1 + rs1;
        m0 = mn0;
        m1 = mn1;

#pragma unroll
        for (int j = 0; j < 8; j++) {
            o[j][0] *= corr0; o[j][1] *= corr0;
            o[j][2] *= corr1; o[j][3] *= corr1;
        }

        if (kt < kt_end) {
#pragma unroll
            for (int it = 0; it < 8; it++) {
                const int sp = vsp + it * 4;
                const float* vb0 = qkv +
                    ((size_t)(((kt + 1) * 64 + 2 * sp) * BATCH + b)) * QKV_N +
                    h * DH + vd2 + 2 * DM;
                vra[it] = *(const float2*)(vb0);
                vrb[it] = *(const float2*)(vb0 + (size_t)BATCH * QKV_N);
            }
        }

        __syncwarp();   // P rows for this warp written only by this warp

#pragma unroll
        for (int ks = 0; ks < 4; ks++) {
            const int c0 = ks * 8 + tig;
            const int c1 = c0 + 4;
            uint32_t ah[4], al[4];
            {
                const uint32_t off =
                    (uint32_t)((pa_row * KS_) + ks * 8 + pa_col) * 4;
                ldsm4(ah, P0a + off);
                ldsm4(al, P1a + off);
            }
#pragma unroll
            for (int j = 0; j < 8; j++) {
                const int n = j * 8 + gid;
                uint32_t bh[2], bl[2];
                bh[0] = V0[(c0) * VS_ + n];
                bh[1] = V0[(c1) * VS_ + n];
                bl[0] = V1[(c0) * VS_ + n];
                bl[1] = V1[(c1) * VS_ + n];
                mma_bf16(o[j], ah, bh);
                mma_bf16(o[j], ah, bl);
                mma_bf16(o[j], al, bh);
            }
        }
    }

    const float inv0 = 1.0f / l0;
    const float inv1 = 1.0f / l1;
    const int r0 = qt * 64 + wid * 16 + gid;
    float* dst0 = av + ((size_t)(r0 * BATCH + b)) * DM + h * DH;
    float* dst8 = dst0 + (size_t)8 * BATCH * DM;
#pragma unroll
    for (int j = 0; j < 8; j++) {
        float2 v;
        v.x = o[j][0] * inv0; v.y = o[j][1] * inv0;
        *(float2*)(dst0 + j * 8 + tig * 2) = v;
        v.x = o[j][2] * inv1; v.y = o[j][3] * inv1;
        *(float2*)(dst8 + j * 8 + tig * 2) = v;
    }
}

// ---------------------------------------------------------------------------
extern "C" void kernel_launch(void* const* d_in, const int* in_sizes, int n_in,
                              void* d_out, int out_size)
{
    const float* x         = (const float*)d_in[0];
    const float* qkv_w     = (const float*)d_in[1];
    const float* qkv_b     = (const float*)d_in[2];
    const float* out_w     = (const float*)d_in[3];
    const float* out_b     = (const float*)d_in[4];
    const int*   is_causal = (const int*)d_in[5];
    float*       out       = (float*)d_out;

    void* qkv_ptr = nullptr;
    void* av_ptr  = nullptr;
    cudaGetSymbolAddress(&qkv_ptr, g_qkv);
    cudaGetSymbolAddress(&av_ptr,  g_av);

    cudaFuncSetAttribute(gemm_bf16x2,
                         cudaFuncAttributeMaxDynamicSharedMemorySize, GEMM_SMEM);
    cudaFuncSetAttribute(flash_attn_tc,
                         cudaFuncAttributeMaxDynamicSharedMemorySize, ATT_SMEM_BYTES);

    // QKV projection: (4096,1024) @ (3072,1024)^T -> (4096,3072)
    {
        dim3 grid(QKV_N / 128, MROWS / 128);
        gemm_bf16x2<<<grid, 256, GEMM_SMEM>>>(x, qkv_w, qkv_b, (float*)qkv_ptr,
                                              MROWS, QKV_N, DM);
    }

    // Attention (bf16x2 tensor-core flash)
    {
        dim3 grid(SEQ / 64, BATCH * NH);
        flash_attn_tc<<<grid, 128, ATT_SMEM_BYTES>>>(
            (const float*)qkv_ptr, is_causal, (float*)av_ptr);
    }

    // Output projection: (4096,1024) @ (1024,1024)^T -> (4096,1024)
    {
        dim3 grid(DM / 128, MROWS / 128);
        gemm_bf16x2<<<grid, 256, GEMM_SMEM>>>((const float*)av_ptr, out_w, out_b, out,
                                              MROWS, DM, DM);
    }
}

// round 17
// speedup vs baseline: 1.0899x; 1.0899x over previous
#include <cuda_runtime.h>
#include <cstdint>

#define SEQ    2048
#define BATCH  2
#define DM     1024
#define NH     16
#define DH     64
#define MROWS  (SEQ * BATCH)      // 4096
#define QKV_N  (3 * DM)           // 3072

// Scratch (allocation-free rule: __device__ globals)
__device__ float    g_qkv[(size_t)MROWS * QKV_N];          // (t*B+b, 3072)
__device__ float    g_av [(size_t)MROWS * DM];             // (t*B+b, 1024)
__device__ uint32_t g_k0[(size_t)MROWS * (DM / 2)];        // K hi, d-packed
__device__ uint32_t g_k1[(size_t)MROWS * (DM / 2)];        // K lo
__device__ uint32_t g_v0[(size_t)BATCH * NH * (SEQ / 2) * DH];  // V hi, s-pair-packed
__device__ uint32_t g_v1[(size_t)BATCH * NH * (SEQ / 2) * DH];  // V lo

// ---------------------------------------------------------------------------
// bf16x2 helpers
// ---------------------------------------------------------------------------
__device__ __forceinline__ void split2bf(float x, float y, uint32_t& h, uint32_t& l) {
    asm("cvt.rn.bf16x2.f32 %0, %1, %2;" : "=r"(h) : "f"(y), "f"(x));
    const float hx = __uint_as_float(h << 16);
    const float hy = __uint_as_float(h & 0xFFFF0000u);
    asm("cvt.rn.bf16x2.f32 %0, %1, %2;" : "=r"(l) : "f"(y - hy), "f"(x - hx));
}
__device__ __forceinline__ void mma_bf16(float* c, const uint32_t* a, const uint32_t* b) {
    asm volatile(
        "mma.sync.aligned.m16n8k16.row.col.f32.bf16.bf16.f32 "
        "{%0,%1,%2,%3}, {%4,%5,%6,%7}, {%8,%9}, {%0,%1,%2,%3};"
        : "+f"(c[0]), "+f"(c[1]), "+f"(c[2]), "+f"(c[3])
        : "r"(a[0]), "r"(a[1]), "r"(a[2]), "r"(a[3]), "r"(b[0]), "r"(b[1]));
}
__device__ __forceinline__ void ldsm4(uint32_t* r, uint32_t saddr) {
    asm volatile("ldmatrix.sync.aligned.m8n8.x4.shared.b16 {%0,%1,%2,%3}, [%4];"
                 : "=r"(r[0]), "=r"(r[1]), "=r"(r[2]), "=r"(r[3]) : "r"(saddr));
}

// ===========================================================================
// Pre-split K and V into packed bf16 hi/lo arrays (memory-bound, ~12 us).
// ===========================================================================
#define SPLIT_ITEMS (MROWS * (DM / 2))    // 2097152 (= V item count too)

__global__ __launch_bounds__(256) void presplit_kv(
    const float* __restrict__ qkv,
    uint32_t* __restrict__ k0, uint32_t* __restrict__ k1,
    uint32_t* __restrict__ v0, uint32_t* __restrict__ v1)
{
    const int idx = blockIdx.x * 256 + threadIdx.x;
    // K: row = qkv row (t*B+b), dp = packed d col
    {
        const int row = idx >> 9;              // / 512
        const int dp  = idx & 511;
        const float2 kv = *(const float2*)(qkv + (size_t)row * QKV_N + DM + 2 * dp);
        uint32_t h, l;
        split2bf(kv.x, kv.y, h, l);
        k0[idx] = h;
        k1[idx] = l;
    }
    // V: idx = ((b*NH + h)*1024 + sp)*64 + d ; packs tokens (2sp, 2sp+1)
    {
        const int d  = idx & 63;
        const int sp = (idx >> 6) & 1023;
        const int h  = (idx >> 16) & 15;
        const int b  = idx >> 20;
        const size_t base = (size_t)((2 * sp) * BATCH + b) * QKV_N + 2 * DM + h * DH + d;
        const float a = qkv[base];
        const float c = qkv[base + (size_t)BATCH * QKV_N];
        uint32_t h2, l2;
        split2bf(a, c, h2, l2);
        v0[idx] = h2;
        v1[idx] = l2;
    }
}

// ===========================================================================
// bf16x2 (3-product) warp-MMA GEMM — exact R11 best config (178 regs).
// CTA 128x128, 8 warps (64x32), K-chunks of 32, per-ks ldmatrix loads.
// ===========================================================================
#define PS 20
#define PTILE (128 * PS)
#define PSTAGE (4 * PTILE)                    // A0,A1,B0,B1
#define GEMM_SMEM (2 * PSTAGE * 4)            // 81920 B

__global__ __launch_bounds__(256, 1) void gemm_bf16x2(
    const float* __restrict__ A, const float* __restrict__ Bw,
    const float* __restrict__ bias, float* __restrict__ C,
    int M, int N, int K)
{
    extern __shared__ uint32_t smu[];
    const uint32_t smem_base = (uint32_t)__cvta_generic_to_shared(smu);

    const int tid  = threadIdx.x;
    const int wid  = tid >> 5;
    const int lane = tid & 31;
    const int gid  = lane >> 2;
    const int tig  = lane & 3;
    const int mw   = (wid & 1) * 64;
    const int nw   = (wid >> 1) * 32;
    const int row0 = blockIdx.y * 128;
    const int col0 = blockIdx.x * 128;

    float acc[4][4][4];
#pragma unroll
    for (int i = 0; i < 4; i++)
#pragma unroll
        for (int j = 0; j < 4; j++)
#pragma unroll
            for (int e = 0; e < 4; e++) acc[i][j][e] = 0.f;

    const int ldr = tid >> 3;
    const int ldc = (tid & 7) << 2;
    const int lcp = (tid & 7) << 1;

    const int a_row = ((lane >> 3) & 1) * 8 + (lane & 7);
    const int a_col = (lane >> 4) * 4;
    const int b_row = (lane >> 4) * 8 + (lane & 7);
    const int b_col = ((lane >> 3) & 1) * 4;

    float4 pa[4], pb[4];
#pragma unroll
    for (int it = 0; it < 4; it++) {
        const int r = ldr + it * 32;
        pa[it] = *(const float4*)(A  + (size_t)(row0 + r) * K + ldc);
        pb[it] = *(const float4*)(Bw + (size_t)(col0 + r) * K + ldc);
    }
    {
        uint32_t* A0 = smu;            uint32_t* A1 = A0 + PTILE;
        uint32_t* B0 = A1 + PTILE;     uint32_t* B1 = B0 + PTILE;
#pragma unroll
        for (int it = 0; it < 4; it++) {
            const int r = ldr + it * 32;
            uint32_t h0, l0, h1, l1;
            split2bf(pa[it].x, pa[it].y, h0, l0);
            split2bf(pa[it].z, pa[it].w, h1, l1);
            *(uint2*)(A0 + r * PS + lcp) = make_uint2(h0, h1);
            *(uint2*)(A1 + r * PS + lcp) = make_uint2(l0, l1);
            split2bf(pb[it].x, pb[it].y, h0, l0);
            split2bf(pb[it].z, pb[it].w, h1, l1);
            *(uint2*)(B0 + r * PS + lcp) = make_uint2(h0, h1);
            *(uint2*)(B1 + r * PS + lcp) = make_uint2(l0, l1);
        }
    }
    const int KCH = K >> 5;
    if (KCH > 1) {
#pragma unroll
        for (int it = 0; it < 4; it++) {
            const int r = ldr + it * 32;
            pa[it] = *(const float4*)(A  + (size_t)(row0 + r) * K + 32 + ldc);
            pb[it] = *(const float4*)(Bw + (size_t)(col0 + r) * K + 32 + ldc);
        }
    }
    __syncthreads();

    for (int kt = 0; kt < KCH; kt++) {
        const uint32_t cur = smem_base + (uint32_t)((kt & 1) * PSTAGE) * 4;
        uint32_t* nxt = smu + ((kt + 1) & 1) * PSTAGE;

        if (kt + 1 < KCH) {
            uint32_t* A0 = nxt;        uint32_t* A1 = A0 + PTILE;
            uint32_t* B0 = A1 + PTILE; uint32_t* B1 = B0 + PTILE;
#pragma unroll
            for (int it = 0; it < 4; it++) {
                const int r = ldr + it * 32;
                uint32_t h0, l0, h1, l1;
                split2bf(pa[it].x, pa[it].y, h0, l0);
                split2bf(pa[it].z, pa[it].w, h1, l1);
                *(uint2*)(A0 + r * PS + lcp) = make_uint2(h0, h1);
                *(uint2*)(A1 + r * PS + lcp) = make_uint2(l0, l1);
                split2bf(pb[it].x, pb[it].y, h0, l0);
                split2bf(pb[it].z, pb[it].w, h1, l1);
                *(uint2*)(B0 + r * PS + lcp) = make_uint2(h0, h1);
                *(uint2*)(B1 + r * PS + lcp) = make_uint2(l0, l1);
            }
        }
        if (kt + 2 < KCH) {
            const int k0n = (kt + 2) << 5;
#pragma unroll
            for (int it = 0; it < 4; it++) {
                const int r = ldr + it * 32;
                pa[it] = *(const float4*)(A  + (size_t)(row0 + r) * K + k0n + ldc);
                pb[it] = *(const float4*)(Bw + (size_t)(col0 + r) * K + k0n + ldc);
            }
        }

        {
            const uint32_t A0a = cur;
            const uint32_t A1a = cur + PTILE * 4;
            const uint32_t B0a = cur + 2 * PTILE * 4;
            const uint32_t B1a = cur + 3 * PTILE * 4;
#pragma unroll
            for (int ks = 0; ks < 2; ks++) {
                uint32_t afh[4][4], afl[4][4], bfh[2][4], bfl[2][4];
#pragma unroll
                for (int i = 0; i < 4; i++) {
                    const uint32_t off =
                        (uint32_t)(((mw + i * 16 + a_row) * PS) + ks * 8 + a_col) * 4;
                    ldsm4(afh[i], A0a + off);
                    ldsm4(afl[i], A1a + off);
                }
#pragma unroll
                for (int jp = 0; jp < 2; jp++) {
                    const uint32_t off =
                        (uint32_t)(((nw + jp * 16 + b_row) * PS) + ks * 8 + b_col) * 4;
                    ldsm4(bfh[jp], B0a + off);
                    ldsm4(bfl[jp], B1a + off);
                }
#pragma unroll
                for (int i = 0; i < 4; i++)
#pragma unroll
                    for (int j = 0; j < 4; j++) {
                        const uint32_t* bh = &bfh[j >> 1][(j & 1) * 2];
                        const uint32_t* bl = &bfl[j >> 1][(j & 1) * 2];
                        mma_bf16(acc[i][j], afh[i], bh);
                        mma_bf16(acc[i][j], afh[i], bl);
                        mma_bf16(acc[i][j], afl[i], bh);
                    }
            }
        }
        __syncthreads();
    }

#pragma unroll
    for (int i = 0; i < 4; i++) {
        const int r = row0 + mw + i * 16 + gid;
#pragma unroll
        for (int j = 0; j < 4; j++) {
            const int ccol = col0 + nw + j * 8 + tig * 2;
            float2 v0, v1;
            v0.x = acc[i][j][0] + bias[ccol];
            v0.y = acc[i][j][1] + bias[ccol + 1];
            v1.x = acc[i][j][2] + bias[ccol];
            v1.y = acc[i][j][3] + bias[ccol + 1];
            *(float2*)(C + (size_t)r * N + ccol)       = v0;
            *(float2*)(C + (size_t)(r + 8) * N + ccol) = v1;
        }
    }
}

// ===========================================================================
// bf16x2 tensor-core flash attention, K/V loaded pre-split (no convert phase).
// ===========================================================================
#define KS_ 36
#define VS_ 72
#define K_TILE (64 * KS_)     // 2304 u32
#define V_TILE (32 * VS_)     // 2304 u32
#define ATT_SMEM_BYTES ((4 * K_TILE + 2 * V_TILE) * 4)   // 55296 B

__global__ __launch_bounds__(128, 2) void flash_attn_tc(
    const float* __restrict__ qkv,
    const uint32_t* __restrict__ gk0, const uint32_t* __restrict__ gk1,
    const uint32_t* __restrict__ gv0, const uint32_t* __restrict__ gv1,
    const int* __restrict__ causal_flag,
    float* __restrict__ av)
{
    extern __shared__ uint32_t smu[];
    uint32_t* K0 = smu;
    uint32_t* K1 = K0 + K_TILE;
    uint32_t* P0 = K1 + K_TILE;
    uint32_t* P1 = P0 + K_TILE;
    uint32_t* V0 = P1 + K_TILE;
    uint32_t* V1 = V0 + V_TILE;
    const uint32_t smem_base = (uint32_t)__cvta_generic_to_shared(smu);
    const uint32_t K0a = smem_base;
    const uint32_t K1a = smem_base + (uint32_t)K_TILE * 4;
    const uint32_t P0a = smem_base + (uint32_t)(2 * K_TILE) * 4;
    const uint32_t P1a = smem_base + (uint32_t)(3 * K_TILE) * 4;

    const int tid  = threadIdx.x;
    const int wid  = tid >> 5;
    const int lane = tid & 31;
    const int gid  = lane >> 2;
    const int tig  = lane & 3;
    const int qt   = blockIdx.x;
    const int b    = blockIdx.y >> 4;
    const int h    = blockIdx.y & 15;
    const int is_causal = *causal_flag;

    const int klr = tid >> 4;            // base row 0..7
    const int kcp = (tid & 15) << 1;     // packed col 0..30
    const int vsp = tid >> 5;            // base packed row 0..3
    const int vd2 = (lane) << 1;         // uint32 col 0..62

    const int kb_row = (lane >> 4) * 8 + (lane & 7);       // + jp*16
    const int kb_col = ((lane >> 3) & 1) * 4;              // + ks*8
    const int pa_row = wid * 16 + ((lane >> 3) & 1) * 8 + (lane & 7);
    const int pa_col = (lane >> 4) * 4;                    // + ks*8

    // V global base for this (b, h)
    const size_t vbase = ((size_t)(b * NH + h)) * (SEQ / 2) * DH;

    uint32_t qp0[4][4], qp1[4][4];
    {
        const int r0 = qt * 64 + wid * 16 + gid;
        const float* q0 = qkv + ((size_t)(r0 * BATCH + b)) * QKV_N + h * DH;
        const float* q8 = q0 + (size_t)8 * BATCH * QKV_N;
#pragma unroll
        for (int ks = 0; ks < 4; ks++) {
            const float2 qa = *(const float2*)(q0 + ks * 16 + tig * 2);
            const float2 qb = *(const float2*)(q8 + ks * 16 + tig * 2);
            const float2 qc = *(const float2*)(q0 + ks * 16 + tig * 2 + 8);
            const float2 qd = *(const float2*)(q8 + ks * 16 + tig * 2 + 8);
            split2bf(qa.x, qa.y, qp0[ks][0], qp1[ks][0]);
            split2bf(qb.x, qb.y, qp0[ks][1], qp1[ks][1]);
            split2bf(qc.x, qc.y, qp0[ks][2], qp1[ks][2]);
            split2bf(qd.x, qd.y, qp0[ks][3], qp1[ks][3]);
        }
    }

    // Prologue: prefetch pre-split K and V tiles for kt = 0.
    uint2 k0r[8], k1r[8], v0r[8], v1r[8];
#pragma unroll
    for (int it = 0; it < 8; it++) {
        const int kr = klr + it * 8;
        const size_t koff = (size_t)(kr * BATCH + b) * (DM / 2) + h * 32 + kcp;
        k0r[it] = *(const uint2*)(gk0 + koff);
        k1r[it] = *(const uint2*)(gk1 + koff);
        const int sp = vsp + it * 4;
        const size_t voff = vbase + (size_t)sp * DH + vd2;
        v0r[it] = *(const uint2*)(gv0 + voff);
        v1r[it] = *(const uint2*)(gv1 + voff);
    }

    float o[8][4];
#pragma unroll
    for (int j = 0; j < 8; j++)
#pragma unroll
        for (int e = 0; e < 4; e++) o[j][e] = 0.f;
    float m0 = -1e30f, m1 = -1e30f, l0 = 0.f, l1 = 0.f;

    const int kt_end = is_causal ? qt : (SEQ / 64 - 1);

    for (int kt = 0; kt <= kt_end; kt++) {
        __syncthreads();
        // ---- store prefetched K/V tiles (pure STS, no conversion) ----
#pragma unroll
        for (int it = 0; it < 8; it++) {
            const int kr = klr + it * 8;
            *(uint2*)(K0 + kr * KS_ + kcp) = k0r[it];
            *(uint2*)(K1 + kr * KS_ + kcp) = k1r[it];
            const int sp = vsp + it * 4;
            *(uint2*)(V0 + sp * VS_ + vd2) = v0r[it];
            *(uint2*)(V1 + sp * VS_ + vd2) = v1r[it];
        }
        __syncthreads();

        // Prefetch next K tile (retires under QK MMAs).
        if (kt < kt_end) {
#pragma unroll
            for (int it = 0; it < 8; it++) {
                const int kr = (kt + 1) * 64 + klr + it * 8;
                const size_t koff = (size_t)(kr * BATCH + b) * (DM / 2) + h * 32 + kcp;
                k0r[it] = *(const uint2*)(gk0 + koff);
                k1r[it] = *(const uint2*)(gk1 + koff);
            }
        }

        // ---- S = Q K^T (3-product bf16x2, ldmatrix K fragments) ----
        float s[8][4];
#pragma unroll
        for (int j = 0; j < 8; j++)
#pragma unroll
            for (int e = 0; e < 4; e++) s[j][e] = 0.f;

#pragma unroll
        for (int ks = 0; ks < 4; ks++) {
            uint32_t kf[4][4], kl[4][4];
#pragma unroll
            for (int jp = 0; jp < 4; jp++) {
                const uint32_t off =
                    (uint32_t)(((jp * 16 + kb_row) * KS_) + ks * 8 + kb_col) * 4;
                ldsm4(kf[jp], K0a + off);
                ldsm4(kl[jp], K1a + off);
            }
#pragma unroll
            for (int j = 0; j < 8; j++) {
                const uint32_t* bh = &kf[j >> 1][(j & 1) * 2];
                const uint32_t* bl = &kl[j >> 1][(j & 1) * 2];
                mma_bf16(s[j], qp0[ks], bh);
                mma_bf16(s[j], qp0[ks], bl);
                mma_bf16(s[j], qp1[ks], bh);
            }
        }

        // ---- scale x8, causal mask ----
#pragma unroll
        for (int j = 0; j < 8; j++)
#pragma unroll
            for (int e = 0; e < 4; e++) s[j][e] *= 8.0f;

        if (is_causal && kt == qt) {
            const int r0 = wid * 16 + gid;
#pragma unroll
            for (int j = 0; j < 8; j++) {
                const int c = j * 8 + tig * 2;
                if (c     > r0)     s[j][0] = -1e30f;
                if (c + 1 > r0)     s[j][1] = -1e30f;
                if (c     > r0 + 8) s[j][2] = -1e30f;
                if (c + 1 > r0 + 8) s[j][3] = -1e30f;
            }
        }

        // ---- online softmax ----
        float rm0 = -1e30f, rm1 = -1e30f;
#pragma unroll
        for (int j = 0; j < 8; j++) {
            rm0 = fmaxf(rm0, fmaxf(s[j][0], s[j][1]));
            rm1 = fmaxf(rm1, fmaxf(s[j][2], s[j][3]));
        }
        rm0 = fmaxf(rm0, __shfl_xor_sync(0xffffffffu, rm0, 1));
        rm0 = fmaxf(rm0, __shfl_xor_sync(0xffffffffu, rm0, 2));
        rm1 = fmaxf(rm1, __shfl_xor_sync(0xffffffffu, rm1, 1));
        rm1 = fmaxf(rm1, __shfl_xor_sync(0xffffffffu, rm1, 2));

        const float mn0 = fmaxf(m0, rm0);
        const float mn1 = fmaxf(m1, rm1);
        const float corr0 = __expf(m0 - mn0);
        const float corr1 = __expf(m1 - mn1);

        float rs0 = 0.f, rs1 = 0.f;
        const int prow = wid * 16 + gid;
#pragma unroll
        for (int j = 0; j < 8; j++) {
            const float p00 = __expf(s[j][0] - mn0);
            const float p01 = __expf(s[j][1] - mn0);
            const float p10 = __expf(s[j][2] - mn1);
            const float p11 = __expf(s[j][3] - mn1);
            rs0 += p00 + p01;
            rs1 += p10 + p11;
            uint32_t hh, ll;
            split2bf(p00, p01, hh, ll);
            P0[prow * KS_ + j * 4 + tig] = hh;
            P1[prow * KS_ + j * 4 + tig] = ll;
            split2bf(p10, p11, hh, ll);
            P0[(prow + 8) * KS_ + j * 4 + tig] = hh;
            P1[(prow + 8) * KS_ + j * 4 + tig] = ll;
        }
        rs0 += __shfl_xor_sync(0xffffffffu, rs0, 1);
        rs0 += __shfl_xor_sync(0xffffffffu, rs0, 2);
        rs1 += __shfl_xor_sync(0xffffffffu, rs1, 1);
        rs1 += __shfl_xor_sync(0xffffffffu, rs1, 2);

        l0 = l0 * corr0 + rs0;
        l1 = l1 * corr1 + rs1;
        m0 = mn0;
        m1 = mn1;

#pragma unroll
        for (int j = 0; j < 8; j++) {
            o[j][0] *= corr0; o[j][1] *= corr0;
            o[j][2] *= corr1; o[j][3] *= corr1;
        }

        // Prefetch next V tile (retires under PV MMAs).
        if (kt < kt_end) {
#pragma unroll
            for (int it = 0; it < 8; it++) {
                const int sp = (kt + 1) * 32 + vsp + it * 4;
                const size_t voff = vbase + (size_t)sp * DH + vd2;
                v0r[it] = *(const uint2*)(gv0 + voff);
                v1r[it] = *(const uint2*)(gv1 + voff);
            }
        }

        __syncwarp();   // P rows for this warp written only by this warp

        // ---- O += P @ V (3-product bf16x2, ldmatrix P fragments) ----
#pragma unroll
        for (int ks = 0; ks < 4; ks++) {
            const int c0 = ks * 8 + tig;
            const int c1 = c0 + 4;
            uint32_t ah[4], al[4];
            {
                const uint32_t off =
                    (uint32_t)((pa_row * KS_) + ks * 8 + pa_col) * 4;
                ldsm4(ah, P0a + off);
                ldsm4(al, P1a + off);
            }
#pragma unroll
            for (int j = 0; j < 8; j++) {
                const int n = j * 8 + gid;
                uint32_t bh[2], bl[2];
                bh[0] = V0[(c0) * VS_ + n];
                bh[1] = V0[(c1) * VS_ + n];
                bl[0] = V1[(c0) * VS_ + n];
                bl[1] = V1[(c1) * VS_ + n];
                mma_bf16(o[j], ah, bh);
                mma_bf16(o[j], ah, bl);
                mma_bf16(o[j], al, bh);
            }
        }
    }

    const float inv0 = 1.0f / l0;
    const float inv1 = 1.0f / l1;
    const int r0 = qt * 64 + wid * 16 + gid;
    float* dst0 = av + ((size_t)(r0 * BATCH + b)) * DM + h * DH;
    float* dst8 = dst0 + (size_t)8 * BATCH * DM;
#pragma unroll
    for (int j = 0; j < 8; j++) {
        float2 v;
        v.x = o[j][0] * inv0; v.y = o[j][1] * inv0;
        *(float2*)(dst0 + j * 8 + tig * 2) = v;
        v.x = o[j][2] * inv1; v.y = o[j][3] * inv1;
        *(float2*)(dst8 + j * 8 + tig * 2) = v;
    }
}

// ---------------------------------------------------------------------------
extern "C" void kernel_launch(void* const* d_in, const int* in_sizes, int n_in,
                              void* d_out, int out_size)
{
    const float* x         = (const float*)d_in[0];
    const float* qkv_w     = (const float*)d_in[1];
    const float* qkv_b     = (const float*)d_in[2];
    const float* out_w     = (const float*)d_in[3];
    const float* out_b     = (const float*)d_in[4];
    const int*   is_causal = (const int*)d_in[5];
    float*       out       = (float*)d_out;

    void *qkv_ptr = nullptr, *av_ptr = nullptr;
    void *k0p = nullptr, *k1p = nullptr, *v0p = nullptr, *v1p = nullptr;
    cudaGetSymbolAddress(&qkv_ptr, g_qkv);
    cudaGetSymbolAddress(&av_ptr,  g_av);
    cudaGetSymbolAddress(&k0p, g_k0);
    cudaGetSymbolAddress(&k1p, g_k1);
    cudaGetSymbolAddress(&v0p, g_v0);
    cudaGetSymbolAddress(&v1p, g_v1);

    cudaFuncSetAttribute(gemm_bf16x2,
                         cudaFuncAttributeMaxDynamicSharedMemorySize, GEMM_SMEM);
    cudaFuncSetAttribute(flash_attn_tc,
                         cudaFuncAttributeMaxDynamicSharedMemorySize, ATT_SMEM_BYTES);

    // QKV projection: (4096,1024) @ (3072,1024)^T -> (4096,3072)
    {
        dim3 grid(QKV_N / 128, MROWS / 128);
        gemm_bf16x2<<<grid, 256, GEMM_SMEM>>>(x, qkv_w, qkv_b, (float*)qkv_ptr,
                                              MROWS, QKV_N, DM);
    }

    // Pre-split K and V into packed bf16 hi/lo
    {
        presplit_kv<<<SPLIT_ITEMS / 256, 256>>>(
            (const float*)qkv_ptr,
            (uint32_t*)k0p, (uint32_t*)k1p, (uint32_t*)v0p, (uint32_t*)v1p);
    }

    // Attention (bf16x2 tensor-core flash, pre-split K/V)
    {
        dim3 grid(SEQ / 64, BATCH * NH);
        flash_attn_tc<<<grid, 128, ATT_SMEM_BYTES>>>(
            (const float*)qkv_ptr,
            (const uint32_t*)k0p, (const uint32_t*)k1p,
            (const uint32_t*)v0p, (const uint32_t*)v1p,
            is_causal, (float*)av_ptr);
    }

    // Output projection: (4096,1024) @ (1024,1024)^T -> (4096,1024)
    {
        dim3 grid(DM / 128, MROWS / 128);
        gemm_bf16x2<<<grid, 256, GEMM_SMEM>>>((const float*)av_ptr, out_w, out_b, out,
                                              MROWS, DM, DM);
    }
}